// round 11
// baseline (speedup 1.0000x reference)
#include <cuda_runtime.h>
#include <cuda_bf16.h>
#include <cstdint>

#define T_LEN 1024
#define NB    1024
#define HID   64
#define NLAY  5
#define NCTA_L 29          // CTAs per layer (one wave: 5*29=145 <= 148)
#define N3    6            // first 6 CTAs: 48 rows (3 mtiles); other 23: 32 rows
#define XPITCH 72          // halfwords per x/h row plane (144B, odd 16B multiple)
#define SX_PLANE (48 * XPITCH)            // 3456 halfwords per plane
#define XBUF_STRIDE (2 * SX_PLANE)        // hi+lo planes per x buffer
#define SH_BASE  (4 * XBUF_STRIDE)        // after 4 x-buffers (halfword idx)
#define SH_PAR   (2 * SX_PLANE)           // halfwords per sH parity (hi+lo)
#define SPERM_OFF ((SH_BASE + 2 * SH_PAR) * 2)    // byte offset of sPerm/sLen
#define SMEM_BYTES (SPERM_OFF + 48 * 2 * 4)
#define GPLANE ((size_t)T_LEN * NB * 32)          // u32 elems per hi/lo plane

// Inter-layer activation sequences, bf16 hi/lo pairs packed 2-per-u32.
__device__ uint32_t g_seq[2][2][GPLANE];
__device__ int g_prog[NLAY * NCTA_L];

// ---------------- helpers ----------------
static __device__ __forceinline__ uint16_t bfbits(__nv_bfloat16 h) {
    return __bfloat16_as_ushort(h);
}
static __device__ __forceinline__ uint32_t bfsplit2(float a, float b, uint32_t* lo) {
    __nv_bfloat16 ha = __float2bfloat16(a), hb = __float2bfloat16(b);
    float ra = a - __bfloat162float(ha);
    float rb = b - __bfloat162float(hb);
    __nv_bfloat16 la = __float2bfloat16(ra), lb = __float2bfloat16(rb);
    *lo = ((uint32_t)bfbits(lb) << 16) | bfbits(la);
    return ((uint32_t)bfbits(hb) << 16) | bfbits(ha);
}
static __device__ __forceinline__ float bflo(uint32_t p) {
    return __bfloat162float(__ushort_as_bfloat16((uint16_t)(p & 0xFFFF)));
}
static __device__ __forceinline__ float bfhi(uint32_t p) {
    return __bfloat162float(__ushort_as_bfloat16((uint16_t)(p >> 16)));
}
static __device__ __forceinline__ void ldsm4(uint32_t a[4], uint32_t addr) {
    asm volatile("ldmatrix.sync.aligned.m8n8.x4.shared.b16 {%0,%1,%2,%3}, [%4];"
                 : "=r"(a[0]), "=r"(a[1]), "=r"(a[2]), "=r"(a[3]) : "r"(addr));
}
static __device__ __forceinline__ void mma_bf16(float c[4], const uint32_t a[4],
                                                const uint32_t b[2]) {
    asm volatile(
        "mma.sync.aligned.m16n8k16.row.col.f32.bf16.bf16.f32 "
        "{%0,%1,%2,%3}, {%4,%5,%6,%7}, {%8,%9}, {%0,%1,%2,%3};"
        : "+f"(c[0]), "+f"(c[1]), "+f"(c[2]), "+f"(c[3])
        : "r"(a[0]), "r"(a[1]), "r"(a[2]), "r"(a[3]), "r"(b[0]), "r"(b[1]));
}
static __device__ __forceinline__ void cp_async16(void* sdst, const void* gsrc) {
    unsigned sa = (unsigned)__cvta_generic_to_shared(sdst);
    asm volatile("cp.async.cg.shared.global [%0], [%1], 16;\n" :: "r"(sa), "l"(gsrc));
}
static __device__ __forceinline__ void cp_async16_s(unsigned sa, const void* gsrc) {
    asm volatile("cp.async.cg.shared.global [%0], [%1], 16;\n" :: "r"(sa), "l"(gsrc));
}
static __device__ __forceinline__ void cp_commit() {
    asm volatile("cp.async.commit_group;\n" ::: "memory");
}
static __device__ __forceinline__ void cp_wait3() {
    asm volatile("cp.async.wait_group 3;\n" ::: "memory");
}
static __device__ __forceinline__ float frcp(float x) {
    float r;
    asm("rcp.approx.ftz.f32 %0, %1;" : "=f"(r) : "f"(x));
    return r;
}
static __device__ __forceinline__ float tanh_f(float x) {
    x = fminf(fmaxf(x, -15.f), 15.f);
    float e = __expf(-2.f * x);
    return __fdividef(1.f - e, 1.f + e);
}
static __device__ __forceinline__ void publish(int* p, int v) {
    asm volatile("st.release.gpu.global.b32 [%0], %1;" :: "l"(p), "r"(v) : "memory");
}
static __device__ __forceinline__ int acq_load(const int* p) {
    int v;
    asm volatile("ld.acquire.gpu.global.b32 %0, [%1];" : "=r"(v) : "l"(p) : "memory");
    return v;
}

// ---------------- embedding gather -> g_seq[0] (+ flag reset) ----------------
__global__ void gather_emb(const int* __restrict__ x, const float* __restrict__ emb) {
    if (blockIdx.x == 0 && threadIdx.x < NLAY * NCTA_L) g_prog[threadIdx.x] = -1;
    size_t e = (size_t)blockIdx.x * 256 + threadIdx.x;   // over T*B*32
    int h2 = e & 31;
    int b  = (e >> 5) & (NB - 1);
    int t  = (int)(e >> 15);
    int xi = x[(size_t)b * T_LEN + t];
    float2 v = ((const float2*)(emb + (size_t)xi * HID))[h2];
    uint32_t lp, hp = bfsplit2(v.x, v.y, &lp);
    size_t o = ((size_t)t * NB + b) * (HID / 2) + h2;
    g_seq[0][0][o] = hp;
    g_seq[0][1][o] = lp;
}

// ---------------- fused one-wave pipelined LSTM, 1 barrier/step ----------------
__global__ void __launch_bounds__(512, 1) lstm_fused(
    const float* __restrict__ Wi, const float* __restrict__ Wf,
    const float* __restrict__ Wg, const float* __restrict__ Wo,
    const float* __restrict__ bi, const float* __restrict__ bf,
    const float* __restrict__ bg, const float* __restrict__ bo,
    const float* __restrict__ init_h, const int* __restrict__ lengths,
    const float* __restrict__ head_w, const float* __restrict__ head_b,
    float* __restrict__ logits)
{
    extern __shared__ __align__(16) uint16_t sm[];
    int* sPerm = (int*)((char*)sm + SPERM_OFF);
    int* sLen  = sPerm + 48;

    const int layer = blockIdx.x / NCTA_L;
    const int gi    = blockIdx.x - layer * NCTA_L;
    const int mc     = (gi < N3) ? 3 : 2;              // mtiles in this CTA
    const int mstart = (gi < N3) ? 48 * gi : 288 + 32 * (gi - N3);
    const int rows   = 16 * mc;
    const int nchunk = 256 * mc;                        // 16B cp.async chunks per buf
    const int in_sel  = layer & 1;
    const int out_sel = in_sel ^ 1;
    const int is_last = (layer == NLAY - 1);
    const int has_src = (layer > 0);

    const int j    = threadIdx.x;
    const int lane = j & 31;
    const int w    = j >> 5;
    const int g    = lane >> 2;     // B-frag column 0..7
    const int tig  = lane & 3;
    const int arow = lane & 15;
    const int acol = (lane >> 4) * 8;
    const int rlow = lane >> 2;                       // row r (0..7)
    const int row_sel = (tig < 2) ? rlow : rlow + 8;  // cell row this lane owns
    const int n0 = 4 * w + 2 * (tig & 1);             // cell cols n0, n0+1
    const int base = (tig < 2) ? 0 : 2;               // C-frag entries for row_sel

    int* my_flag        = &g_prog[layer * NCTA_L + gi];
    const int* src_flag = &g_prog[(layer - 1) * NCTA_L + gi];
    int avail_c = -1;

    // ---- sort rows by length (ascending): rank sort, deterministic ----
    if (j < rows) {
        int Lr = lengths[mstart + j];
        int rank = 0;
        for (int s = 0; s < rows; s++) {
            int Ls = lengths[mstart + s];
            rank += (Ls < Lr) || (Ls == Lr && s < j);
        }
        sPerm[rank] = j;
        sLen[rank]  = Lr;
    }

    // ---- weight B-fragments (hi/lo), gate-interleaved column mapping ----
    // nt=0 covers gates {i(cols 0-3), f(cols 4-7)}, nt=1 {g, o}; n = 4w + (g&3).
    uint32_t whi[2][8][2], wlo[2][8][2];
    float bia[2][2];
#pragma unroll
    for (int nt = 0; nt < 2; nt++) {
        int gate = nt * 2 + (g >= 4);
        int nc   = 4 * w + (g & 3);
        const float* Wr =
            (gate == 0 ? Wi : gate == 1 ? Wf : gate == 2 ? Wg : Wo) +
            (size_t)(layer * HID + nc) * 128;
#pragma unroll
        for (int kt = 0; kt < 8; kt++) {
            int k0 = 16 * kt + 2 * tig;
            whi[nt][kt][0] = bfsplit2(Wr[k0],     Wr[k0 + 1], &wlo[nt][kt][0]);
            whi[nt][kt][1] = bfsplit2(Wr[k0 + 8], Wr[k0 + 9], &wlo[nt][kt][1]);
        }
        // bias for this lane's C-frag columns (gate depends on tig, not g)
        int bg_ = nt * 2 + (tig >= 2);
        const float* Bb = (bg_ == 0 ? bi : bg_ == 1 ? bf : bg_ == 2 ? bg : bo);
        bia[nt][0] = Bb[layer * HID + n0];
        bia[nt][1] = Bb[layer * HID + n0 + 1];
    }
    __syncthreads();   // sPerm/sLen ready

    // ---- per-lane cell state: (row_sel, n0..n0+1) per mtile ----
    float cst[6];
    uint32_t hp_c[3], lp_c[3];
    int len_sel[3], lenmt[3];
    uint32_t* gout[3];
    {
        float h0a = tanh_f(init_h[layer * HID + n0]);
        float h0b = tanh_f(init_h[layer * HID + n0 + 1]);
        uint32_t lp0, hp0 = bfsplit2(h0a, h0b, &lp0);
#pragma unroll
        for (int q = 0; q < 3; q++) {
            len_sel[q] = 0; lenmt[q] = 0;
            hp_c[q] = hp0; lp_c[q] = lp0;
            cst[2 * q] = 0.f; cst[2 * q + 1] = 0.f;
            gout[q] = nullptr;
            if (q < mc) {
                len_sel[q] = sLen[q * 16 + row_sel];
                lenmt[q]   = sLen[q * 16 + 15];
                gout[q] = &g_seq[out_sel][0][
                    (size_t)(mstart + sPerm[q * 16 + row_sel]) * 32 + 2 * w + (tig & 1)];
            }
        }
    }

    // ---- x source pointers (per chunk), positioned at t=4 ----
    const uint32_t* xsrc[2];
    unsigned xdst[2];
    int xlen[2];
#pragma unroll
    for (int q = 0; q < 2; q++) {
        xsrc[q] = nullptr; xlen[q] = 0; xdst[q] = 0;
        int c = q * 512 + j;
        if (c < nchunk) {
            int r = c >> 4, sub = c & 15, hl = sub >> 3, ch = sub & 7;
            xlen[q] = sLen[r];
            xsrc[q] = &g_seq[in_sel][hl][((size_t)4 * NB + mstart + sPerm[r]) * 32 + ch * 4];
            xdst[q] = (unsigned)__cvta_generic_to_shared(
                sm + hl * SX_PLANE + r * XPITCH + ch * 8);
        }
    }

    // prologue gate: wait for producer lead of ~13 steps
    if (has_src && j == 0) {
        int v = -1;
        while (v < 12) { v = acq_load(src_flag); if (v < 12) __nanosleep(40); }
        avail_c = v;
    }
    __syncthreads();   // hold all threads until producer is ahead

    // prefetch x(0..3) into buffers 0..3, one commit group each
#pragma unroll
    for (int tt = 0; tt < 4; tt++) {
#pragma unroll
        for (int q = 0; q < 2; q++) {
            int c = q * 512 + j;
            if (c < nchunk) {
                int r = c >> 4, sub = c & 15, hl = sub >> 3, ch = sub & 7;
                cp_async16(sm + tt * XBUF_STRIDE + hl * SX_PLANE + r * XPITCH + ch * 8,
                           &g_seq[in_sel][hl][((size_t)tt * NB + mstart + sPerm[r]) * 32 + ch * 4]);
            }
        }
        cp_commit();
    }

    // h0 into sH parity 0 (each lane stores its (row_sel, n0) slot per mtile)
#pragma unroll
    for (int q = 0; q < 3; q++) if (q < mc) {
        int hw = SH_BASE + (q * 16 + row_sel) * XPITCH + n0;
        *(uint32_t*)(sm + hw)            = hp_c[q];
        *(uint32_t*)(sm + hw + SX_PLANE) = lp_c[q];
    }
    cp_wait3();          // x(0) landed
    __syncthreads();

    // prologue x-GEMM(0) from buffer 0 into cxa
    float cxa[3][2][4];
#pragma unroll
    for (int mt = 0; mt < 3; mt++) if (mt < mc) {
#pragma unroll
        for (int nt = 0; nt < 2; nt++) {
            cxa[mt][nt][0] = bia[nt][0]; cxa[mt][nt][1] = bia[nt][1];
            cxa[mt][nt][2] = bia[nt][0]; cxa[mt][nt][3] = bia[nt][1];
        }
        uint32_t bHi = (uint32_t)__cvta_generic_to_shared(
            sm + 0 * SX_PLANE + (mt * 16 + arow) * XPITCH + acol);
        uint32_t bLo = (uint32_t)__cvta_generic_to_shared(
            sm + 1 * SX_PLANE + (mt * 16 + arow) * XPITCH + acol);
#pragma unroll
        for (int kt = 0; kt < 4; kt++) {
            uint32_t ah[4], al[4];
            ldsm4(ah, bHi + kt * 32);
            ldsm4(al, bLo + kt * 32);
            mma_bf16(cxa[mt][0], ah, whi[0][kt]);
            mma_bf16(cxa[mt][1], ah, whi[1][kt]);
            mma_bf16(cxa[mt][0], ah, wlo[0][kt]);
            mma_bf16(cxa[mt][1], ah, wlo[1][kt]);
            mma_bf16(cxa[mt][0], al, whi[0][kt]);
            mma_bf16(cxa[mt][1], al, whi[1][kt]);
        }
    }

    for (int t = 0; t < T_LEN; t++) {
        // publish h(t-1): stores ordered by previous bottom barrier
        if (!is_last && j == 0 && t >= 1) publish(my_flag, t - 1);

        // prefetch x(t+4) into buf t&3 (acquire for it done last step)
        if (t + 4 < T_LEN) {
            unsigned boff = (unsigned)(t & 3) * (XBUF_STRIDE * 2);
#pragma unroll
            for (int q = 0; q < 2; q++)
                if (t + 4 < xlen[q]) cp_async16_s(xdst[q] + boff, xsrc[q]);
        }
#pragma unroll
        for (int q = 0; q < 2; q++) xsrc[q] += NB * 32;
        cp_commit();

        // ======== h-GEMM(t) from sH parity t&1 (kt 4..7) into cxa ========
        {
            int hbase = SH_BASE + (t & 1) * SH_PAR;
#pragma unroll
            for (int mt = 0; mt < 3; mt++) if (mt < mc && t < lenmt[mt]) {
                uint32_t bHi = (uint32_t)__cvta_generic_to_shared(
                    sm + hbase + (mt * 16 + arow) * XPITCH + acol);
                uint32_t bLo = bHi + SX_PLANE * 2;
#pragma unroll
                for (int kt = 4; kt < 8; kt++) {
                    uint32_t ah[4], al[4];
                    ldsm4(ah, bHi + (kt - 4) * 32);
                    ldsm4(al, bLo + (kt - 4) * 32);
                    mma_bf16(cxa[mt][0], ah, whi[0][kt]);
                    mma_bf16(cxa[mt][1], ah, whi[1][kt]);
                    mma_bf16(cxa[mt][0], ah, wlo[0][kt]);
                    mma_bf16(cxa[mt][1], ah, wlo[1][kt]);
                    mma_bf16(cxa[mt][0], al, whi[0][kt]);
                    mma_bf16(cxa[mt][1], al, whi[1][kt]);
                }
            }
        }
        cp_wait3();        // x(t+1) resident

        // ======== per-mtile: warp-local cell(t) then x-GEMM(t+1) ========
        const int bx = (t + 1) & 3;
        const int hstore = SH_BASE + ((t + 1) & 1) * SH_PAR;
#pragma unroll
        for (int u = 0; u < 3; u++) if (u < mc) {
            if (t <= lenmt[u]) {
                // exchange partner-gate values: lane^2 holds the other gate
                float s00 = cxa[u][0][(base ^ 2) + 0], s01 = cxa[u][0][(base ^ 2) + 1];
                float s10 = cxa[u][1][(base ^ 2) + 0], s11 = cxa[u][1][(base ^ 2) + 1];
                float r00 = __shfl_xor_sync(0xffffffffu, s00, 2);
                float r01 = __shfl_xor_sync(0xffffffffu, s01, 2);
                float r10 = __shfl_xor_sync(0xffffffffu, s10, 2);
                float r11 = __shfl_xor_sync(0xffffffffu, s11, 2);
                if (t < len_sel[u]) {
                    float o00 = cxa[u][0][base + 0], o01 = cxa[u][0][base + 1];
                    float o10 = cxa[u][1][base + 0], o11 = cxa[u][1][base + 1];
                    bool lo2 = (tig < 2);
                    float pi0 = lo2 ? o00 : r00, pi1 = lo2 ? o01 : r01;
                    float pf0 = lo2 ? r00 : o00, pf1 = lo2 ? r01 : o01;
                    float pg0 = lo2 ? o10 : r10, pg1 = lo2 ? o11 : r11;
                    float po0 = lo2 ? r10 : o10, po1 = lo2 ? r11 : o11;
                    // element 0
                    float ea0 = __expf(-pi0), eb0 = __expf(-pf0);
                    float ec0 = __expf(-po0), ed0 = __expf(-2.f * pg0);
                    float u0 = 1.f + ea0, v0 = 1.f + eb0, w0 = 1.f + ec0, z0 = 1.f + ed0;
                    float R10 = frcp(u0 * v0), R20 = frcp(w0 * z0);
                    float si0 = R10 * v0, sf0 = R10 * u0;
                    float so0 = R20 * z0, tg0 = 2.f * (R20 * w0) - 1.f;
                    float c0n = sf0 * cst[2 * u] + si0 * tg0;
                    // element 1
                    float ea1 = __expf(-pi1), eb1 = __expf(-pf1);
                    float ec1 = __expf(-po1), ed1 = __expf(-2.f * pg1);
                    float u1 = 1.f + ea1, v1 = 1.f + eb1, w1 = 1.f + ec1, z1 = 1.f + ed1;
                    float R11 = frcp(u1 * v1), R21 = frcp(w1 * z1);
                    float si1 = R11 * v1, sf1 = R11 * u1;
                    float so1 = R21 * z1, tg1 = 2.f * (R21 * w1) - 1.f;
                    float c1n = sf1 * cst[2 * u + 1] + si1 * tg1;
                    // tanh(c) paired
                    float cc0 = fminf(fmaxf(c0n, -15.f), 15.f);
                    float cc1 = fminf(fmaxf(c1n, -15.f), 15.f);
                    float e0 = __expf(-2.f * cc0), e1 = __expf(-2.f * cc1);
                    float a0 = 1.f + e0, a1 = 1.f + e1;
                    float R3 = frcp(a0 * a1);
                    float th0 = (1.f - e0) * (R3 * a1);
                    float th1 = (1.f - e1) * (R3 * a0);
                    cst[2 * u] = c0n; cst[2 * u + 1] = c1n;
                    hp_c[u] = bfsplit2(so0 * th0, so1 * th1, &lp_c[u]);
                }
                if (t <= len_sel[u]) {
                    int hw = hstore + (u * 16 + row_sel) * XPITCH + n0;
                    *(uint32_t*)(sm + hw)            = hp_c[u];
                    *(uint32_t*)(sm + hw + SX_PLANE) = lp_c[u];
                    if (!is_last) {
                        gout[u][0]      = hp_c[u];
                        gout[u][GPLANE] = lp_c[u];
                    }
                }
            }

            // ---- x-GEMM(t+1) for mt=u ----
            if (t + 1 < lenmt[u]) {
#pragma unroll
                for (int nt = 0; nt < 2; nt++) {
                    cxa[u][nt][0] = bia[nt][0]; cxa[u][nt][1] = bia[nt][1];
                    cxa[u][nt][2] = bia[nt][0]; cxa[u][nt][3] = bia[nt][1];
                }
                uint32_t bHi = (uint32_t)__cvta_generic_to_shared(
                    sm + bx * XBUF_STRIDE + 0 * SX_PLANE + (u * 16 + arow) * XPITCH + acol);
                uint32_t bLo = bHi + SX_PLANE * 2;
#pragma unroll
                for (int kt = 0; kt < 4; kt++) {
                    uint32_t ah[4], al[4];
                    ldsm4(ah, bHi + kt * 32);
                    ldsm4(al, bLo + kt * 32);
                    mma_bf16(cxa[u][0], ah, whi[0][kt]);
                    mma_bf16(cxa[u][1], ah, whi[1][kt]);
                    mma_bf16(cxa[u][0], ah, wlo[0][kt]);
                    mma_bf16(cxa[u][1], ah, wlo[1][kt]);
                    mma_bf16(cxa[u][0], al, whi[0][kt]);
                    mma_bf16(cxa[u][1], al, whi[1][kt]);
                }
            }
        }
#pragma unroll
        for (int q = 0; q < 3; q++) if (q < mc) gout[q] += NB * 32;

        // acquire lookahead for next step's prefetch x(t+5)
        if (has_src && j == 0) {
            int need = t + 5;
            if (need < T_LEN && avail_c < need) {
                int v = acq_load(src_flag);
                while (v < need) { __nanosleep(40); v = acq_load(src_flag); }
                avail_c = v;
            }
        }
        __syncthreads();   // single per-step barrier
    }
    if (!is_last && j == 0) publish(my_flag, T_LEN - 1);

    // ---- head on last layer (h recovered as hi+lo; un-permute rows) ----
    if (is_last) {
        float* hsc = (float*)sm;   // x buffers are dead; reuse as [48][64] floats
#pragma unroll
        for (int q = 0; q < 3; q++) if (q < mc) {
            int row = q * 16 + row_sel;
            hsc[row * HID + n0]     = bflo(hp_c[q]) + bflo(lp_c[q]);
            hsc[row * HID + n0 + 1] = bfhi(hp_c[q]) + bfhi(lp_c[q]);
        }
        __syncthreads();
        if (j < rows) {
            float s = 0.f;
#pragma unroll
            for (int k = 0; k < HID; k++) s += hsc[j * HID + k] * head_w[k];
            logits[mstart + sPerm[j]] = s + head_b[0];
        }
    }
}

extern "C" void kernel_launch(void* const* d_in, const int* in_sizes, int n_in,
                              void* d_out, int out_size) {
    const int*   x       = (const int*)d_in[0];
    const int*   lengths = (const int*)d_in[1];
    const float* emb     = (const float*)d_in[2];
    const float* Wi      = (const float*)d_in[3];
    const float* Wf      = (const float*)d_in[4];
    const float* Wg      = (const float*)d_in[5];
    const float* Wo      = (const float*)d_in[6];
    const float* bi      = (const float*)d_in[7];
    const float* bf      = (const float*)d_in[8];
    const float* bg      = (const float*)d_in[9];
    const float* bo      = (const float*)d_in[10];
    const float* init_h  = (const float*)d_in[11];
    const float* head_w  = (const float*)d_in[12];
    const float* head_b  = (const float*)d_in[13];
    float* logits = (float*)d_out;

    cudaFuncSetAttribute(lstm_fused, cudaFuncAttributeMaxDynamicSharedMemorySize,
                         SMEM_BYTES);

    gather_emb<<<(size_t)T_LEN * NB * 32 / 256, 256>>>(x, emb);
    lstm_fused<<<NLAY * NCTA_L, 512, SMEM_BYTES>>>(
        Wi, Wf, Wg, Wo, bi, bf, bg, bo,
        init_h, lengths, head_w, head_b, logits);
}

// round 12
// speedup vs baseline: 1.2063x; 1.2063x over previous
#include <cuda_runtime.h>
#include <cuda_bf16.h>
#include <cstdint>

#define T_LEN 1024
#define NB    1024
#define HID   64
#define NLAY  5
#define NCTA_L 29          // CTAs per layer (one wave: 5*29=145 <= 148)
#define NMT   64           // 16-row mtiles over the sorted batch
#define XPITCH 72          // halfwords per x/h row plane (144B, odd 16B multiple)
#define PPITCH 264         // floats per pre-activation row
#define SX_PLANE (48 * XPITCH)            // 3456 halfwords per plane
#define XBUF_STRIDE (2 * SX_PLANE)        // hi+lo planes per x buffer
#define SH_BASE  (4 * XBUF_STRIDE)        // after 4 x-buffers
#define SPRE_OFF ((SH_BASE + 2 * SX_PLANE) * 2)   // byte offset of sPre
#define SPERM_OFF (SPRE_OFF + 48 * PPITCH * 4)    // byte offset of sPerm/sLen/sPartLo
#define SMEM_BYTES (SPERM_OFF + (48 * 2 + 32) * 4)
#define GPLANE ((size_t)T_LEN * NB * 32)          // u32 elems per hi/lo plane
#define INF_I 0x3fffffff

// Inter-layer activation sequences, bf16 hi/lo pairs packed 2-per-u32.
__device__ uint32_t g_seq[2][2][GPLANE];
__device__ int g_prog[NLAY * NCTA_L];

// ---------------- helpers ----------------
static __device__ __forceinline__ uint16_t bfbits(__nv_bfloat16 h) {
    return __bfloat16_as_ushort(h);
}
static __device__ __forceinline__ uint32_t bfsplit2(float a, float b, uint32_t* lo) {
    __nv_bfloat16 ha = __float2bfloat16(a), hb = __float2bfloat16(b);
    float ra = a - __bfloat162float(ha);
    float rb = b - __bfloat162float(hb);
    __nv_bfloat16 la = __float2bfloat16(ra), lb = __float2bfloat16(rb);
    *lo = ((uint32_t)bfbits(lb) << 16) | bfbits(la);
    return ((uint32_t)bfbits(hb) << 16) | bfbits(ha);
}
static __device__ __forceinline__ float bflo(uint32_t p) {
    return __bfloat162float(__ushort_as_bfloat16((uint16_t)(p & 0xFFFF)));
}
static __device__ __forceinline__ float bfhi(uint32_t p) {
    return __bfloat162float(__ushort_as_bfloat16((uint16_t)(p >> 16)));
}
static __device__ __forceinline__ void ldsm4(uint32_t a[4], uint32_t addr) {
    asm volatile("ldmatrix.sync.aligned.m8n8.x4.shared.b16 {%0,%1,%2,%3}, [%4];"
                 : "=r"(a[0]), "=r"(a[1]), "=r"(a[2]), "=r"(a[3]) : "r"(addr));
}
static __device__ __forceinline__ void mma_bf16(float c[4], const uint32_t a[4],
                                                const uint32_t b[2]) {
    asm volatile(
        "mma.sync.aligned.m16n8k16.row.col.f32.bf16.bf16.f32 "
        "{%0,%1,%2,%3}, {%4,%5,%6,%7}, {%8,%9}, {%0,%1,%2,%3};"
        : "+f"(c[0]), "+f"(c[1]), "+f"(c[2]), "+f"(c[3])
        : "r"(a[0]), "r"(a[1]), "r"(a[2]), "r"(a[3]), "r"(b[0]), "r"(b[1]));
}
static __device__ __forceinline__ void cp_async16(void* sdst, const void* gsrc) {
    unsigned sa = (unsigned)__cvta_generic_to_shared(sdst);
    asm volatile("cp.async.cg.shared.global [%0], [%1], 16;\n" :: "r"(sa), "l"(gsrc));
}
static __device__ __forceinline__ void cp_async16_s(unsigned sa, const void* gsrc) {
    asm volatile("cp.async.cg.shared.global [%0], [%1], 16;\n" :: "r"(sa), "l"(gsrc));
}
static __device__ __forceinline__ void cp_commit() {
    asm volatile("cp.async.commit_group;\n" ::: "memory");
}
static __device__ __forceinline__ void cp_wait3() {
    asm volatile("cp.async.wait_group 3;\n" ::: "memory");
}
static __device__ __forceinline__ float frcp(float x) {
    float r;
    asm("rcp.approx.ftz.f32 %0, %1;" : "=f"(r) : "f"(x));
    return r;
}
static __device__ __forceinline__ float tanh_f(float x) {
    x = fminf(fmaxf(x, -15.f), 15.f);
    float e = __expf(-2.f * x);
    return __fdividef(1.f - e, 1.f + e);
}
static __device__ __forceinline__ void publish(int* p, int v) {
    asm volatile("st.release.gpu.global.b32 [%0], %1;" :: "l"(p), "r"(v) : "memory");
}
static __device__ __forceinline__ int acq_load(const int* p) {
    int v;
    asm volatile("ld.acquire.gpu.global.b32 %0, [%1];" : "=r"(v) : "l"(p) : "memory");
    return v;
}

// ---------------- embedding gather -> g_seq[0] (+ flag reset) ----------------
__global__ void gather_emb(const int* __restrict__ x, const float* __restrict__ emb) {
    if (blockIdx.x == 0 && threadIdx.x < NLAY * NCTA_L) g_prog[threadIdx.x] = -1;
    size_t e = (size_t)blockIdx.x * 256 + threadIdx.x;   // over T*B*32
    int h2 = e & 31;
    int b  = (e >> 5) & (NB - 1);
    int t  = (int)(e >> 15);
    int xi = x[(size_t)b * T_LEN + t];
    float2 v = ((const float2*)(emb + (size_t)xi * HID))[h2];
    uint32_t lp, hp = bfsplit2(v.x, v.y, &lp);
    size_t o = ((size_t)t * NB + b) * (HID / 2) + h2;
    g_seq[0][0][o] = hp;
    g_seq[0][1][o] = lp;
}

// ---------------- fused one-wave pipelined LSTM, globally load-balanced ----------------
__global__ void __launch_bounds__(512, 1) lstm_fused(
    const float* __restrict__ Wi, const float* __restrict__ Wf,
    const float* __restrict__ Wg, const float* __restrict__ Wo,
    const float* __restrict__ bi, const float* __restrict__ bf,
    const float* __restrict__ bg, const float* __restrict__ bo,
    const float* __restrict__ init_h, const int* __restrict__ lengths,
    const float* __restrict__ head_w, const float* __restrict__ head_b,
    float* __restrict__ logits)
{
    extern __shared__ __align__(16) uint16_t sm[];
    float* sPre = (float*)((char*)sm + SPRE_OFF);
    int* sPerm   = (int*)((char*)sm + SPERM_OFF);   // [48] rank -> original row
    int* sLen    = sPerm + 48;                      // [48] sorted lengths
    int* sPartLo = sLen + 48;                       // [30] mtile partition bounds

    // temp overlay in x-buffer region (dead until prefetch)
    int* tKey     = (int*)sm;         // [1024]
    int* tPermAll = tKey + 1024;      // [1024]
    int* tSort    = tPermAll + 1024;  // [1024]
    int* tC       = tSort + 1024;     // [64]
    int* tS       = tC + 64;          // [65]
    int* tD       = tS + 65;          // [30*65]
    int* tCh      = tD + 30 * 65;     // [30*65]

    const int layer = blockIdx.x / NCTA_L;
    const int gi    = blockIdx.x - layer * NCTA_L;
    const int in_sel  = layer & 1;
    const int out_sel = in_sel ^ 1;
    const int is_last = (layer == NLAY - 1);
    const int has_src = (layer > 0);

    const int j    = threadIdx.x;
    const int lane = j & 31;
    const int w    = j >> 5;
    const int g    = lane >> 2;
    const int tig  = lane & 3;
    const int arow = lane & 15;
    const int acol = (lane >> 4) * 8;

    int* my_flag        = &g_prog[layer * NCTA_L + gi];
    const int* src_flag = &g_prog[(layer - 1) * NCTA_L + gi];
    int avail_c = -1;

    // ======== global sort of all 1024 rows by (length, row) ========
#pragma unroll
    for (int q = 0; q < 2; q++) {
        int r = q * 512 + j;
        tKey[r] = lengths[r] * 1024 + r;
    }
    __syncthreads();
#pragma unroll
    for (int q = 0; q < 2; q++) {
        int r = q * 512 + j;
        int K = tKey[r];
        int rank = 0;
        for (int s = 0; s < 1024; s += 4) {
            int4 v4 = *(const int4*)&tKey[s];
            rank += (v4.x < K) + (v4.y < K) + (v4.z < K) + (v4.w < K);
        }
        tPermAll[rank] = r;
        tSort[rank]    = K >> 10;
    }
    __syncthreads();

    // ======== DP minimax partition of 64 mtiles into 29 parts (1..3 each) ========
    if (j < NMT) tC[j] = tSort[16 * j + 15];
    __syncthreads();
    if (j == 0) {
        tS[0] = 0;
        for (int m = 0; m < NMT; m++) tS[m + 1] = tS[m] + tC[m];
    }
    if (j <= NMT) tD[j] = (j == 0) ? 0 : INF_I;
    __syncthreads();
    for (int p = 1; p <= NCTA_L; p++) {
        if (j <= NMT) {
            int best = INF_I, bk = 0;
#pragma unroll
            for (int k = 1; k <= 3; k++) {
                if (j >= k) {
                    int prev = tD[(p - 1) * 65 + j - k];
                    int pc   = (tS[j] - tS[j - k]) * 5 + 6 * tC[j - 1];
                    int val  = prev > pc ? prev : pc;
                    if (val < best) { best = val; bk = k; }
                }
            }
            tD[p * 65 + j]  = best;
            tCh[p * 65 + j] = bk;
        }
        __syncthreads();
    }
    if (j == 0) {
        int i = NMT;
        sPartLo[NCTA_L] = NMT;
        for (int p = NCTA_L; p >= 1; p--) {
            int k = tCh[p * 65 + i];
            i -= k;
            sPartLo[p - 1] = i;
        }
    }
    __syncthreads();
    const int mtlo = sPartLo[gi];
    const int mc   = sPartLo[gi + 1] - mtlo;   // 1..3 mtiles
    const int gstart = 16 * mtlo;
    const int rows   = 16 * mc;
    const int nchunk = 256 * mc;
    if (j < rows) {
        sPerm[j] = tPermAll[gstart + j];
        sLen[j]  = tSort[gstart + j];
    }

    // ---- weight B-fragments (hi/lo) in registers, biases ----
    uint32_t whi[2][8][2], wlo[2][8][2];
    float be[2], bo_[2];
#pragma unroll
    for (int nt = 0; nt < 2; nt++) {
        int jo   = 16 * w + 8 * nt + g;
        int gate = jo >> 6, nc = jo & 63;
        const float* Wr =
            (gate == 0 ? Wi : gate == 1 ? Wf : gate == 2 ? Wg : Wo) +
            (size_t)(layer * HID + nc) * 128;
#pragma unroll
        for (int kt = 0; kt < 8; kt++) {
            int k0 = 16 * kt + 2 * tig;
            whi[nt][kt][0] = bfsplit2(Wr[k0],     Wr[k0 + 1], &wlo[nt][kt][0]);
            whi[nt][kt][1] = bfsplit2(Wr[k0 + 8], Wr[k0 + 9], &wlo[nt][kt][1]);
        }
        int je = 16 * w + 8 * nt + 2 * tig;
        int ge = je >> 6, ne = je & 63;
        be[nt] = (ge == 0 ? bi : ge == 1 ? bf : ge == 2 ? bg : bo)[layer * HID + ne];
        int jo2 = je + 1;
        int go2 = jo2 >> 6, no2 = jo2 & 63;
        bo_[nt] = (go2 == 0 ? bi : go2 == 1 ? bf : go2 == 2 ? bg : bo)[layer * HID + no2];
    }
    __syncthreads();   // sPerm/sLen ready; temps free after prefetch begins below

    // ---- per-thread cell rows: p = q*512+j -> (ml = p>>5, np = p&31) ----
    float cst[6];
    uint32_t hp_c[3], lp_c[3];
    int lenq[3], lenmt[3];
    uint32_t* gout[3];
#pragma unroll
    for (int q = 0; q < 3; q++) {
        lenq[q] = 0; lenmt[q] = 0;
        hp_c[q] = 0; lp_c[q] = 0;
        cst[2 * q] = 0.f; cst[2 * q + 1] = 0.f;
        gout[q] = nullptr;
        if (q < mc) {
            int p = q * 512 + j, ml = p >> 5, np = p & 31;
            lenq[q]  = sLen[ml];
            lenmt[q] = sLen[q * 16 + 15];
            float h0a = tanh_f(init_h[layer * HID + 2 * np]);
            float h0b = tanh_f(init_h[layer * HID + 2 * np + 1]);
            hp_c[q] = bfsplit2(h0a, h0b, &lp_c[q]);
            gout[q] = &g_seq[out_sel][0][(size_t)sPerm[ml] * 32 + np];
        }
    }
    const int maxlen = sLen[rows - 1];

    // ---- x source pointers (per chunk), positioned at t=4 ----
    const uint32_t* xsrc[2];
    unsigned xdst[2];
    int xlen[2];
#pragma unroll
    for (int q = 0; q < 2; q++) {
        xsrc[q] = nullptr; xlen[q] = 0; xdst[q] = 0;
        int c = q * 512 + j;
        if (c < nchunk) {
            int r = c >> 4, sub = c & 15, hl = sub >> 3, ch = sub & 7;
            xlen[q] = sLen[r];
            xsrc[q] = &g_seq[in_sel][hl][((size_t)4 * NB + sPerm[r]) * 32 + ch * 4];
            xdst[q] = (unsigned)__cvta_generic_to_shared(
                sm + hl * SX_PLANE + r * XPITCH + ch * 8);
        }
    }

    // prologue gate: wait for producer lead of ~13 steps (or its completion)
    if (has_src && j == 0) {
        int v = -1;
        while (v < 12) { v = acq_load(src_flag); if (v < 12) __nanosleep(40); }
        avail_c = v;
    }
    __syncthreads();   // hold all threads until producer is ahead

    // prefetch x(0..3) into buffers 0..3 (overwrites temp region — safe now)
#pragma unroll
    for (int tt = 0; tt < 4; tt++) {
#pragma unroll
        for (int q = 0; q < 2; q++) {
            int c = q * 512 + j;
            if (c < nchunk) {
                int r = c >> 4, sub = c & 15, hl = sub >> 3, ch = sub & 7;
                cp_async16(sm + tt * XBUF_STRIDE + hl * SX_PLANE + r * XPITCH + ch * 8,
                           &g_seq[in_sel][hl][((size_t)tt * NB + sPerm[r]) * 32 + ch * 4]);
            }
        }
        cp_commit();
    }

    // h0 into sH
#pragma unroll
    for (int q = 0; q < 3; q++) if (q < mc) {
        int p = q * 512 + j, ml = p >> 5, np = p & 31;
        *(uint32_t*)(sm + SH_BASE + 0 * SX_PLANE + ml * XPITCH + 2 * np) = hp_c[q];
        *(uint32_t*)(sm + SH_BASE + 1 * SX_PLANE + ml * XPITCH + 2 * np) = lp_c[q];
    }
    cp_wait3();          // x(0) landed
    __syncthreads();

    // prologue x-GEMM(0) from buffer 0 into cxa
    float cxa[3][2][4];
#pragma unroll
    for (int mt = 0; mt < 3; mt++) if (mt < mc) {
#pragma unroll
        for (int nt = 0; nt < 2; nt++) {
            cxa[mt][nt][0] = be[nt]; cxa[mt][nt][1] = bo_[nt];
            cxa[mt][nt][2] = be[nt]; cxa[mt][nt][3] = bo_[nt];
        }
        uint32_t bHi = (uint32_t)__cvta_generic_to_shared(
            sm + 0 * SX_PLANE + (mt * 16 + arow) * XPITCH + acol);
        uint32_t bLo = (uint32_t)__cvta_generic_to_shared(
            sm + 1 * SX_PLANE + (mt * 16 + arow) * XPITCH + acol);
#pragma unroll
        for (int kt = 0; kt < 4; kt++) {
            uint32_t ah[4], al[4];
            ldsm4(ah, bHi + kt * 32);
            ldsm4(al, bLo + kt * 32);
            mma_bf16(cxa[mt][0], ah, whi[0][kt]);
            mma_bf16(cxa[mt][1], ah, whi[1][kt]);
            mma_bf16(cxa[mt][0], ah, wlo[0][kt]);
            mma_bf16(cxa[mt][1], ah, wlo[1][kt]);
            mma_bf16(cxa[mt][0], al, whi[0][kt]);
            mma_bf16(cxa[mt][1], al, whi[1][kt]);
        }
    }

    const int col0 = 16 * w + 2 * tig;

    for (int t = 0; t < maxlen; t++) {
        // early publish of h(t-1): stores ordered by previous bottom barrier
        if (!is_last && j == 0 && t >= 1) publish(my_flag, t - 1);

        // ======== PHASE 1: h-GEMM(t) (kt 4..7) into cxa, store pre ========
#pragma unroll
        for (int mt = 0; mt < 3; mt++) if (mt < mc && t < lenmt[mt]) {
            uint32_t bHi = (uint32_t)__cvta_generic_to_shared(
                sm + SH_BASE + 0 * SX_PLANE + (mt * 16 + arow) * XPITCH + acol);
            uint32_t bLo = bHi + SX_PLANE * 2;
#pragma unroll
            for (int kt = 4; kt < 8; kt++) {
                uint32_t ah[4], al[4];
                ldsm4(ah, bHi + (kt - 4) * 32);
                ldsm4(al, bLo + (kt - 4) * 32);
                mma_bf16(cxa[mt][0], ah, whi[0][kt]);
                mma_bf16(cxa[mt][1], ah, whi[1][kt]);
                mma_bf16(cxa[mt][0], ah, wlo[0][kt]);
                mma_bf16(cxa[mt][1], ah, wlo[1][kt]);
                mma_bf16(cxa[mt][0], al, whi[0][kt]);
                mma_bf16(cxa[mt][1], al, whi[1][kt]);
            }
            *(float2*)&sPre[(mt * 16 + g) * PPITCH + col0] =
                make_float2(cxa[mt][0][0], cxa[mt][0][1]);
            *(float2*)&sPre[(mt * 16 + g + 8) * PPITCH + col0] =
                make_float2(cxa[mt][0][2], cxa[mt][0][3]);
            *(float2*)&sPre[(mt * 16 + g) * PPITCH + col0 + 8] =
                make_float2(cxa[mt][1][0], cxa[mt][1][1]);
            *(float2*)&sPre[(mt * 16 + g + 8) * PPITCH + col0 + 8] =
                make_float2(cxa[mt][1][2], cxa[mt][1][3]);
        }
        // gate for x(t+4) (only while some row still consumes it)
        if (has_src && j == 0) {
            int need = t + 4;
            if (need < maxlen && avail_c < need) {
                int v = acq_load(src_flag);
                while (v < need) { __nanosleep(40); v = acq_load(src_flag); }
                avail_c = v;
            }
        }
        __syncthreads();   // MID: pre visible; acquire ordered before prefetch

        // ======== PHASE 2: prefetch x(t+4); interleaved x-GEMM(t+1) + cell(t) ========
        {
            unsigned boff = (unsigned)(t & 3) * (XBUF_STRIDE * 2);
#pragma unroll
            for (int q = 0; q < 2; q++)
                if (t + 4 < xlen[q]) cp_async16_s(xdst[q] + boff, xsrc[q]);
        }
#pragma unroll
        for (int q = 0; q < 2; q++) xsrc[q] += NB * 32;
        cp_commit();
        cp_wait3();        // x(t+1) resident

        const int bx = (t + 1) & 3;
#pragma unroll
        for (int u = 0; u < 3; u++) if (u < mc) {
            // ---- x-GEMM(t+1) for mt=u (skipped when tile fully frozen) ----
            if (t + 1 < lenmt[u]) {
#pragma unroll
                for (int nt = 0; nt < 2; nt++) {
                    cxa[u][nt][0] = be[nt]; cxa[u][nt][1] = bo_[nt];
                    cxa[u][nt][2] = be[nt]; cxa[u][nt][3] = bo_[nt];
                }
                uint32_t bHi = (uint32_t)__cvta_generic_to_shared(
                    sm + bx * XBUF_STRIDE + 0 * SX_PLANE + (u * 16 + arow) * XPITCH + acol);
                uint32_t bLo = bHi + SX_PLANE * 2;
#pragma unroll
                for (int kt = 0; kt < 4; kt++) {
                    uint32_t ah[4], al[4];
                    ldsm4(ah, bHi + kt * 32);
                    ldsm4(al, bLo + kt * 32);
                    mma_bf16(cxa[u][0], ah, whi[0][kt]);
                    mma_bf16(cxa[u][1], ah, whi[1][kt]);
                    mma_bf16(cxa[u][0], ah, wlo[0][kt]);
                    mma_bf16(cxa[u][1], ah, wlo[1][kt]);
                    mma_bf16(cxa[u][0], al, whi[0][kt]);
                    mma_bf16(cxa[u][1], al, whi[1][kt]);
                }
            }

            // ---- cell(t) for q=u (warp-uniform freeze-skip) ----
            if (t < lenq[u]) {
                int p = u * 512 + j, ml = p >> 5, np = p & 31;
                float2 pi2 = *(const float2*)&sPre[ml * PPITCH + 2 * np];
                float2 pf2 = *(const float2*)&sPre[ml * PPITCH + 64 + 2 * np];
                float2 pg2 = *(const float2*)&sPre[ml * PPITCH + 128 + 2 * np];
                float2 po2 = *(const float2*)&sPre[ml * PPITCH + 192 + 2 * np];
                // element 0
                float ea0 = __expf(-pi2.x), eb0 = __expf(-pf2.x);
                float ec0 = __expf(-po2.x), ed0 = __expf(-2.f * pg2.x);
                float u0 = 1.f + ea0, v0 = 1.f + eb0, w0 = 1.f + ec0, z0 = 1.f + ed0;
                float R10 = frcp(u0 * v0), R20 = frcp(w0 * z0);
                float si0 = R10 * v0, sf0 = R10 * u0;
                float so0 = R20 * z0, tg0 = 2.f * (R20 * w0) - 1.f;
                float c0n = sf0 * cst[2 * u] + si0 * tg0;
                // element 1
                float ea1 = __expf(-pi2.y), eb1 = __expf(-pf2.y);
                float ec1 = __expf(-po2.y), ed1 = __expf(-2.f * pg2.y);
                float u1 = 1.f + ea1, v1 = 1.f + eb1, w1 = 1.f + ec1, z1 = 1.f + ed1;
                float R11 = frcp(u1 * v1), R21 = frcp(w1 * z1);
                float si1 = R11 * v1, sf1 = R11 * u1;
                float so1 = R21 * z1, tg1 = 2.f * (R21 * w1) - 1.f;
                float c1n = sf1 * cst[2 * u + 1] + si1 * tg1;
                // tanh(c) paired across the two elements
                float cc0 = fminf(fmaxf(c0n, -15.f), 15.f);
                float cc1 = fminf(fmaxf(c1n, -15.f), 15.f);
                float e0 = __expf(-2.f * cc0), e1 = __expf(-2.f * cc1);
                float a0 = 1.f + e0, a1 = 1.f + e1;
                float R3 = frcp(a0 * a1);
                float th0 = (1.f - e0) * (R3 * a1);
                float th1 = (1.f - e1) * (R3 * a0);
                float h0n = so0 * th0, h1n = so1 * th1;
                cst[2 * u] = c0n; cst[2 * u + 1] = c1n;
                hp_c[u] = bfsplit2(h0n, h1n, &lp_c[u]);
                *(uint32_t*)(sm + SH_BASE + 0 * SX_PLANE + ml * XPITCH + 2 * np) = hp_c[u];
                *(uint32_t*)(sm + SH_BASE + 1 * SX_PLANE + ml * XPITCH + 2 * np) = lp_c[u];
                if (!is_last) {
                    gout[u][0]      = hp_c[u];
                    gout[u][GPLANE] = lp_c[u];
                }
            }
        }
#pragma unroll
        for (int q = 0; q < 3; q++) if (q < mc) gout[q] += NB * 32;

        __syncthreads();   // BOTTOM: h(t) visible for phase1(t+1)
    }
    if (!is_last && j == 0) publish(my_flag, T_LEN - 1);

    // ---- head on last layer (h recovered as hi+lo; un-permute rows) ----
    if (is_last) {
#pragma unroll
        for (int q = 0; q < 3; q++) if (q < mc) {
            int p = q * 512 + j, ml = p >> 5, np = p & 31;
            sPre[ml * HID + 2 * np]     = bflo(hp_c[q]) + bflo(lp_c[q]);
            sPre[ml * HID + 2 * np + 1] = bfhi(hp_c[q]) + bfhi(lp_c[q]);
        }
        __syncthreads();
        if (j < rows) {
            float s = 0.f;
#pragma unroll
            for (int k = 0; k < HID; k++) s += sPre[j * HID + k] * head_w[k];
            logits[sPerm[j]] = s + head_b[0];
        }
    }
}

extern "C" void kernel_launch(void* const* d_in, const int* in_sizes, int n_in,
                              void* d_out, int out_size) {
    const int*   x       = (const int*)d_in[0];
    const int*   lengths = (const int*)d_in[1];
    const float* emb     = (const float*)d_in[2];
    const float* Wi      = (const float*)d_in[3];
    const float* Wf      = (const float*)d_in[4];
    const float* Wg      = (const float*)d_in[5];
    const float* Wo      = (const float*)d_in[6];
    const float* bi      = (const float*)d_in[7];
    const float* bf      = (const float*)d_in[8];
    const float* bg      = (const float*)d_in[9];
    const float* bo      = (const float*)d_in[10];
    const float* init_h  = (const float*)d_in[11];
    const float* head_w  = (const float*)d_in[12];
    const float* head_b  = (const float*)d_in[13];
    float* logits = (float*)d_out;

    cudaFuncSetAttribute(lstm_fused, cudaFuncAttributeMaxDynamicSharedMemorySize,
                         SMEM_BYTES);

    gather_emb<<<(size_t)T_LEN * NB * 32 / 256, 256>>>(x, emb);
    lstm_fused<<<NLAY * NCTA_L, 512, SMEM_BYTES>>>(
        Wi, Wf, Wg, Wo, bi, bf, bg, bo,
        init_h, lengths, head_w, head_b, logits);
}